// round 14
// baseline (speedup 1.0000x reference)
#include <cuda_runtime.h>
#include <cuda_fp8.h>
#include <cstdint>

#define NB 2
#define NH 16
#define NS 2048
#define ND 128
#define PITCHB 144         // bytes per smem row (128 data + 16 pad): conflict-free ldmatrix
#define NW 512             // n-window per CTA
#define NT 4               // K tiles per CTA

// fp8 e4m3 scratch (unscaled), row-major [bh][s][d]
__device__ __align__(16) unsigned char g_q8[(size_t)NB * NH * NS * ND];
__device__ __align__(16) unsigned char g_k8[(size_t)NB * NH * NS * ND];

// ---------------------------------------------------------------------------
// Prepass: fp32 -> e4m3 (no scaling; head scale folded into epilogue)
// ---------------------------------------------------------------------------
__global__ void prep_kernel(const float* __restrict__ q, const float* __restrict__ k) {
    size_t e = ((size_t)blockIdx.x * 256 + threadIdx.x) * 8;
    const float* src = blockIdx.y ? k : q;
    unsigned char* dst = blockIdx.y ? g_k8 : g_q8;
    float4 v0 = ((const float4*)(src + e))[0];
    float4 v1 = ((const float4*)(src + e))[1];
    uint32_t p0 = __nv_cvt_float2_to_fp8x2(make_float2(v0.x, v0.y), __NV_SATFINITE, __NV_E4M3);
    uint32_t p1 = __nv_cvt_float2_to_fp8x2(make_float2(v0.z, v0.w), __NV_SATFINITE, __NV_E4M3);
    uint32_t p2 = __nv_cvt_float2_to_fp8x2(make_float2(v1.x, v1.y), __NV_SATFINITE, __NV_E4M3);
    uint32_t p3 = __nv_cvt_float2_to_fp8x2(make_float2(v1.z, v1.w), __NV_SATFINITE, __NV_E4M3);
    uint2 w;
    w.x = (p0 & 0xFFFFu) | (p1 << 16);
    w.y = (p2 & 0xFFFFu) | (p3 << 16);
    *(uint2*)(dst + e) = w;
}

// ---------------------------------------------------------------------------
// PTX helpers
// ---------------------------------------------------------------------------
__device__ __forceinline__ void cp16(uint32_t saddr, const void* g) {
    asm volatile("cp.async.cg.shared.global [%0], [%1], 16;" :: "r"(saddr), "l"(g));
}

__device__ __forceinline__ void ldm4(uint32_t* d, uint32_t addr) {
    asm volatile("ldmatrix.sync.aligned.m8n8.x4.shared.b16 {%0,%1,%2,%3}, [%4];"
                 : "=r"(d[0]), "=r"(d[1]), "=r"(d[2]), "=r"(d[3]) : "r"(addr));
}

__device__ __forceinline__ void mma32(float* c, const uint32_t* a, uint32_t b0, uint32_t b1) {
    asm volatile("mma.sync.aligned.m16n8k32.row.col.f32.e4m3.e4m3.f32 "
                 "{%0,%1,%2,%3}, {%4,%5,%6,%7}, {%8,%9}, {%0,%1,%2,%3};"
                 : "+f"(c[0]), "+f"(c[1]), "+f"(c[2]), "+f"(c[3])
                 : "r"(a[0]), "r"(a[1]), "r"(a[2]), "r"(a[3]), "r"(b0), "r"(b1));
}

// SMEM byte offsets (fp8 tiles, 144 B rows)
#define TILE_B   (128 * PITCHB)             // 18432
#define Q_OFF    0
#define K0_OFF   TILE_B
#define K1_OFF   (2 * TILE_B)
#define K2_OFF   (3 * TILE_B)
#define PQ_OFF   (4 * TILE_B)               // 73728
#define PK_OFF   (PQ_OFF + 512)
#define SMEM_BYTES (PK_OFF + 2048)          // 76288 -> 2 CTAs/SM

// ---------------------------------------------------------------------------
// Main: per CTA one 128-row Q tile x 4 K-tiles, triple-buffered cp.async,
// one barrier per tile, A fragments hoisted to registers for the whole CTA.
// fp8 m16n8k32 mma, scale folded in epilogue, shfl-paired STG.128 stores.
//   grid = (4 n-quarters, 16 m-tiles, 32 bh), 256 threads, 2 CTAs/SM
// ---------------------------------------------------------------------------
__global__ __launch_bounds__(256, 2)
void alibi_gemm(const float* __restrict__ hs, const float* __restrict__ slopes,
                const float* __restrict__ positions, const int* __restrict__ tok,
                float* __restrict__ out) {
    extern __shared__ unsigned char smem[];
    const uint32_t sbase = (uint32_t)__cvta_generic_to_shared(smem);
    float* pq = (float*)(smem + PQ_OFF);
    float* pk = (float*)(smem + PK_OFF);

    const int tid  = threadIdx.x;
    const int lane = tid & 31;
    const int warp = tid >> 5;
    const int bh   = blockIdx.z;
    const int b    = bh >> 4;
    const int m0   = blockIdx.y * 128;
    const int nb   = blockIdx.x * NW;
    const float slope = slopes[bh & 15];
    const float sc = hs[bh & 15] * 0.08838834764831845f;   // head_scale / sqrt(128)

    // separable ALiBi bias vectors
    if (tid < 128)
        pq[tid] = slope * positions[tok[b * NS + m0 + tid]];
    #pragma unroll
    for (int i = 0; i < NW / 256; i++)
        pk[tid + i * 256] = slope * positions[tok[b * NS + nb + tid + i * 256]];

    const unsigned char* qsrc = g_q8 + ((size_t)bh * NS + m0) * ND;
    const unsigned char* ksrc = g_k8 + ((size_t)bh * NS + nb) * ND;

    // tile = 128 rows x 128 B = 1024 x 16B chunks; thread owns 4 chunks
    const int ld_row = tid >> 3, ld_col = (tid & 7) * 16;
    #pragma unroll
    for (int i = 0; i < 4; i++)
        cp16(sbase + Q_OFF + (ld_row + i * 32) * PITCHB + ld_col,
             qsrc + (ld_row + i * 32) * 128 + ld_col);
    #pragma unroll
    for (int i = 0; i < 4; i++)
        cp16(sbase + K0_OFF + (ld_row + i * 32) * PITCHB + ld_col,
             ksrc + (ld_row + i * 32) * 128 + ld_col);
    asm volatile("cp.async.commit_group;");          // G0 = {Q, K0}
    #pragma unroll
    for (int i = 0; i < 4; i++)
        cp16(sbase + K1_OFF + (ld_row + i * 32) * PITCHB + ld_col,
             ksrc + (size_t)(128 + ld_row + i * 32) * 128 + ld_col);
    asm volatile("cp.async.commit_group;");          // G1 = {K1}

    const int warp_m = (warp >> 1) * 32;   // 0,32,64,96
    const int warp_n = (warp & 1) * 64;    // 0,64

    // ldmatrix bases (byte offsets, rows 144 B)
    const uint32_t a_base = sbase + Q_OFF
        + (uint32_t)((warp_m + (lane & 15)) * PITCHB + (lane >> 4) * 16);
    const uint32_t b_off = (uint32_t)(
        (warp_n + (lane & 7) + ((lane >> 4) << 3)) * PITCHB + ((lane >> 3) & 1) * 16);

    // rotating buffer registers: cur (mma), nxt, n2 (refill target at tile start)
    uint32_t ld_cur = sbase + K0_OFF + b_off;
    uint32_t ld_nxt = sbase + K1_OFF + b_off;
    uint32_t ld_n2  = sbase + K2_OFF + b_off;

    const bool odd = lane & 1;
    const int wc_base = warp_n + ((lane >> 1) & 1) * 4 + (odd ? 8 : 0);

    // A fragments: loaded once at t=0, reused for all K tiles (Q is invariant)
    uint32_t Areg[2][4][4];

    // loop-carried epilogue pointers
    const float* pkt = pk;
    float* obase = out + ((size_t)bh * NS + m0) * NS + nb;

    #pragma unroll 1
    for (int t = 0; t < NT; t++) {
        if (t == NT - 1) asm volatile("cp.async.wait_group 0;");
        else             asm volatile("cp.async.wait_group 1;");
        __syncthreads();   // K(t) visible; all warps done with buffer of t-1

        if (t == 0) {
            // hoisted A loads (Q arrived with G0)
            #pragma unroll
            for (int ks = 0; ks < 4; ks++) {
                ldm4(Areg[0][ks], a_base + ks * 32);
                ldm4(Areg[1][ks], a_base + ks * 32 + 16 * PITCHB);
            }
        }

        // earliest possible refill: t+2 into the buffer last used at t-1
        if (t + 2 < NT) {
            const unsigned char* src = ksrc + (size_t)(t + 2) * 128 * 128;
            const uint32_t dstb = ld_n2 - b_off;
            #pragma unroll
            for (int i = 0; i < 4; i++)
                cp16(dstb + (ld_row + i * 32) * PITCHB + ld_col,
                     src + (ld_row + i * 32) * 128 + ld_col);
            asm volatile("cp.async.commit_group;");
        }

        float acc[2][8][4];
        #pragma unroll
        for (int mi = 0; mi < 2; mi++)
            #pragma unroll
            for (int nf = 0; nf < 8; nf++)
                #pragma unroll
                for (int r = 0; r < 4; r++)
                    acc[mi][nf][r] = 0.0f;

        const uint32_t bb = ld_cur;
        #pragma unroll
        for (int ks = 0; ks < 4; ks++) {             // k32 steps -> K=128
            #pragma unroll
            for (int g = 0; g < 4; g++) {
                uint32_t Bv[4];
                ldm4(Bv, bb + g * (16 * PITCHB) + ks * 32);
                mma32(acc[0][2 * g],     Areg[0][ks], Bv[0], Bv[1]);
                mma32(acc[0][2 * g + 1], Areg[0][ks], Bv[2], Bv[3]);
                mma32(acc[1][2 * g],     Areg[1][ks], Bv[0], Bv[1]);
                mma32(acc[1][2 * g + 1], Areg[1][ks], Bv[2], Bv[3]);
            }
        }

        // epilogue: v = acc*sc + (pk_j - pq_i); pair-exchange via shfl; STG.128
        float2 pkc0[4], pkc1[4];
        #pragma unroll
        for (int g = 0; g < 4; g++) {
            const int c0 = warp_n + g * 16 + (lane & 3) * 2;
            pkc0[g] = *(const float2*)(pkt + c0);
            pkc1[g] = *(const float2*)(pkt + c0 + 8);
        }
        #pragma unroll
        for (int mi = 0; mi < 2; mi++) {
            const int r = warp_m + mi * 16 + (lane >> 2);
            const float pq0 = pq[r], pq1 = pq[r + 8];
            float* orow = obase + (size_t)r * NS;
            #pragma unroll
            for (int g = 0; g < 4; g++) {
                float2 a0 = make_float2(fmaf(acc[mi][2 * g][0], sc, pkc0[g].x - pq0),
                                        fmaf(acc[mi][2 * g][1], sc, pkc0[g].y - pq0));
                float2 a1 = make_float2(fmaf(acc[mi][2 * g + 1][0], sc, pkc1[g].x - pq0),
                                        fmaf(acc[mi][2 * g + 1][1], sc, pkc1[g].y - pq0));
                float2 b0 = make_float2(fmaf(acc[mi][2 * g][2], sc, pkc0[g].x - pq1),
                                        fmaf(acc[mi][2 * g][3], sc, pkc0[g].y - pq1));
                float2 b1 = make_float2(fmaf(acc[mi][2 * g + 1][2], sc, pkc1[g].x - pq1),
                                        fmaf(acc[mi][2 * g + 1][3], sc, pkc1[g].y - pq1));
                float2 sa = odd ? a0 : a1;
                float2 sb = odd ? b0 : b1;
                float2 ra, rb;
                ra.x = __shfl_xor_sync(0xFFFFFFFF, sa.x, 1);
                ra.y = __shfl_xor_sync(0xFFFFFFFF, sa.y, 1);
                rb.x = __shfl_xor_sync(0xFFFFFFFF, sb.x, 1);
                rb.y = __shfl_xor_sync(0xFFFFFFFF, sb.y, 1);
                const int wc = wc_base + g * 16;
                float4 v0 = odd ? make_float4(ra.x, ra.y, a1.x, a1.y)
                                : make_float4(a0.x, a0.y, ra.x, ra.y);
                float4 v1 = odd ? make_float4(rb.x, rb.y, b1.x, b1.y)
                                : make_float4(b0.x, b0.y, rb.x, rb.y);
                __stcs((float4*)(orow + wc), v0);
                __stcs((float4*)(orow + (size_t)8 * NS + wc), v1);
            }
        }

        // advance loop-carried pointers; rotate buffers
        pkt += 128;
        obase += 128;
        uint32_t tmp = ld_cur;
        ld_cur = ld_nxt;
        ld_nxt = ld_n2;
        ld_n2  = tmp;
    }
}

// ---------------------------------------------------------------------------
// Launch
// ---------------------------------------------------------------------------
extern "C" void kernel_launch(void* const* d_in, const int* in_sizes, int n_in,
                              void* d_out, int out_size) {
    const float* q           = (const float*)d_in[0];
    const float* k           = (const float*)d_in[1];
    const float* head_scales = (const float*)d_in[2];
    const float* slopes      = (const float*)d_in[3];
    const float* positions   = (const float*)d_in[4];
    const int*   tok         = (const int*)d_in[5];
    float*       out         = (float*)d_out;

    // 8.39M floats per tensor / 8 per thread = 4096 blocks x 256
    prep_kernel<<<dim3(4096, 2), 256>>>(q, k);

    cudaFuncSetAttribute(alibi_gemm, cudaFuncAttributeMaxDynamicSharedMemorySize, SMEM_BYTES);
    alibi_gemm<<<dim3(4, 16, 32), 256, SMEM_BYTES>>>(head_scales, slopes, positions, tok, out);
}

// round 15
// speedup vs baseline: 1.1957x; 1.1957x over previous
#include <cuda_runtime.h>
#include <cuda_fp8.h>
#include <cstdint>

#define NB 2
#define NH 16
#define NS 2048
#define ND 128
#define PITCHB 144         // bytes per smem row (128 data + 16 pad): conflict-free ldmatrix
#define NW 256             // n-window per CTA
#define NT 4               // 64-col K steps per CTA

// fp8 e4m3 scratch (unscaled), row-major [bh][s][d]
__device__ __align__(16) unsigned char g_q8[(size_t)NB * NH * NS * ND];
__device__ __align__(16) unsigned char g_k8[(size_t)NB * NH * NS * ND];

// ---------------------------------------------------------------------------
// Prepass: fp32 -> e4m3 (no scaling; head scale folded into epilogue)
// ---------------------------------------------------------------------------
__global__ void prep_kernel(const float* __restrict__ q, const float* __restrict__ k) {
    size_t e = ((size_t)blockIdx.x * 256 + threadIdx.x) * 8;
    const float* src = blockIdx.y ? k : q;
    unsigned char* dst = blockIdx.y ? g_k8 : g_q8;
    float4 v0 = ((const float4*)(src + e))[0];
    float4 v1 = ((const float4*)(src + e))[1];
    uint32_t p0 = __nv_cvt_float2_to_fp8x2(make_float2(v0.x, v0.y), __NV_SATFINITE, __NV_E4M3);
    uint32_t p1 = __nv_cvt_float2_to_fp8x2(make_float2(v0.z, v0.w), __NV_SATFINITE, __NV_E4M3);
    uint32_t p2 = __nv_cvt_float2_to_fp8x2(make_float2(v1.x, v1.y), __NV_SATFINITE, __NV_E4M3);
    uint32_t p3 = __nv_cvt_float2_to_fp8x2(make_float2(v1.z, v1.w), __NV_SATFINITE, __NV_E4M3);
    uint2 w;
    w.x = (p0 & 0xFFFFu) | (p1 << 16);
    w.y = (p2 & 0xFFFFu) | (p3 << 16);
    *(uint2*)(dst + e) = w;
}

// ---------------------------------------------------------------------------
// PTX helpers
// ---------------------------------------------------------------------------
__device__ __forceinline__ void cp16(uint32_t saddr, const void* g) {
    asm volatile("cp.async.cg.shared.global [%0], [%1], 16;" :: "r"(saddr), "l"(g));
}

__device__ __forceinline__ void ldm4(uint32_t* d, uint32_t addr) {
    asm volatile("ldmatrix.sync.aligned.m8n8.x4.shared.b16 {%0,%1,%2,%3}, [%4];"
                 : "=r"(d[0]), "=r"(d[1]), "=r"(d[2]), "=r"(d[3]) : "r"(addr));
}

__device__ __forceinline__ void mma32(float* c, const uint32_t* a, uint32_t b0, uint32_t b1) {
    asm volatile("mma.sync.aligned.m16n8k32.row.col.f32.e4m3.e4m3.f32 "
                 "{%0,%1,%2,%3}, {%4,%5,%6,%7}, {%8,%9}, {%0,%1,%2,%3};"
                 : "+f"(c[0]), "+f"(c[1]), "+f"(c[2]), "+f"(c[3])
                 : "r"(a[0]), "r"(a[1]), "r"(a[2]), "r"(a[3]), "r"(b0), "r"(b1));
}

// SMEM byte offsets (fp8 tiles, 144 B rows). K step tile = 64 rows.
#define QTILE_B  (128 * PITCHB)             // 18432
#define KTILE_B  (64 * PITCHB)              // 9216
#define Q_OFF    0
#define K0_OFF   QTILE_B
#define K1_OFF   (K0_OFF + KTILE_B)
#define K2_OFF   (K1_OFF + KTILE_B)
#define PQ_OFF   (K2_OFF + KTILE_B)         // 46080
#define PK_OFF   (PQ_OFF + 512)
#define SMEM_BYTES (PK_OFF + 1024)          // 47616 -> 3 CTAs/SM

// ---------------------------------------------------------------------------
// Main: per CTA one 128-row Q tile x 4 K-steps of 64 cols, triple-buffered
// cp.async, one barrier per step, warp tile 32x32 (acc=32 regs -> 3 CTAs/SM).
// fp8 m16n8k32 mma, scale folded in epilogue, shfl-paired STG.128 stores.
//   grid = (8 n-windows, 16 m-tiles, 32 bh), 256 threads, 3 CTAs/SM
// ---------------------------------------------------------------------------
__global__ __launch_bounds__(256, 3)
void alibi_gemm(const float* __restrict__ hs, const float* __restrict__ slopes,
                const float* __restrict__ positions, const int* __restrict__ tok,
                float* __restrict__ out) {
    extern __shared__ unsigned char smem[];
    const uint32_t sbase = (uint32_t)__cvta_generic_to_shared(smem);
    float* pq = (float*)(smem + PQ_OFF);
    float* pk = (float*)(smem + PK_OFF);

    const int tid  = threadIdx.x;
    const int lane = tid & 31;
    const int warp = tid >> 5;
    const int bh   = blockIdx.z;
    const int b    = bh >> 4;
    const int m0   = blockIdx.y * 128;
    const int nb   = blockIdx.x * NW;
    const float slope = slopes[bh & 15];
    const float sc = hs[bh & 15] * 0.08838834764831845f;   // head_scale / sqrt(128)

    // separable ALiBi bias vectors
    if (tid < 128)
        pq[tid] = slope * positions[tok[b * NS + m0 + tid]];
    if (tid < NW)
        pk[tid] = slope * positions[tok[b * NS + nb + tid]];

    const unsigned char* qsrc = g_q8 + ((size_t)bh * NS + m0) * ND;
    const unsigned char* ksrc = g_k8 + ((size_t)bh * NS + nb) * ND;

    // Q tile: 128 rows x 8 chunks = 1024 chunks, 4 per thread
    const int ld_row = tid >> 3, ld_col = (tid & 7) * 16;
    #pragma unroll
    for (int i = 0; i < 4; i++)
        cp16(sbase + Q_OFF + (ld_row + i * 32) * PITCHB + ld_col,
             qsrc + (ld_row + i * 32) * 128 + ld_col);
    // K step tiles: 64 rows x 8 chunks = 512 chunks, 2 per thread
    #pragma unroll
    for (int i = 0; i < 2; i++)
        cp16(sbase + K0_OFF + (ld_row + i * 32) * PITCHB + ld_col,
             ksrc + (ld_row + i * 32) * 128 + ld_col);
    asm volatile("cp.async.commit_group;");          // G0 = {Q, K0}
    #pragma unroll
    for (int i = 0; i < 2; i++)
        cp16(sbase + K1_OFF + (ld_row + i * 32) * PITCHB + ld_col,
             ksrc + (size_t)(64 + ld_row + i * 32) * 128 + ld_col);
    asm volatile("cp.async.commit_group;");          // G1 = {K1}

    const int warp_m = (warp >> 1) * 32;   // 0,32,64,96
    const int warp_n = (warp & 1) * 32;    // 0,32

    // ldmatrix bases (byte offsets, rows 144 B)
    const uint32_t a_base = sbase + Q_OFF
        + (uint32_t)((warp_m + (lane & 15)) * PITCHB + (lane >> 4) * 16);
    const uint32_t b_off = (uint32_t)(
        (warp_n + (lane & 7) + ((lane >> 4) << 3)) * PITCHB + ((lane >> 3) & 1) * 16);

    // rotating buffer registers: cur (mma), nxt, n2 (refill target at step start)
    uint32_t ld_cur = sbase + K0_OFF + b_off;
    uint32_t ld_nxt = sbase + K1_OFF + b_off;
    uint32_t ld_n2  = sbase + K2_OFF + b_off;

    const bool odd = lane & 1;
    const int wc_base = warp_n + ((lane >> 1) & 1) * 4 + (odd ? 8 : 0);

    // loop-carried epilogue pointers
    const float* pkt = pk;
    float* obase = out + ((size_t)bh * NS + m0) * NS + nb;

    #pragma unroll 1
    for (int t = 0; t < NT; t++) {
        if (t == NT - 1) asm volatile("cp.async.wait_group 0;");
        else             asm volatile("cp.async.wait_group 1;");
        __syncthreads();   // K(t) visible; all warps done with buffer of t-1

        // earliest possible refill: t+2 into the buffer last used at t-1
        if (t + 2 < NT) {
            const unsigned char* src = ksrc + (size_t)(t + 2) * 64 * 128;
            const uint32_t dstb = ld_n2 - b_off;
            #pragma unroll
            for (int i = 0; i < 2; i++)
                cp16(dstb + (ld_row + i * 32) * PITCHB + ld_col,
                     src + (ld_row + i * 32) * 128 + ld_col);
            asm volatile("cp.async.commit_group;");
        }

        float acc[2][4][4];
        #pragma unroll
        for (int mi = 0; mi < 2; mi++)
            #pragma unroll
            for (int nf = 0; nf < 4; nf++)
                #pragma unroll
                for (int r = 0; r < 4; r++)
                    acc[mi][nf][r] = 0.0f;

        const uint32_t bb = ld_cur;
        #pragma unroll
        for (int ks = 0; ks < 4; ks++) {             // k32 steps -> K=128
            uint32_t A0[4], A1[4], Bv0[4], Bv1[4];
            ldm4(A0, a_base + ks * 32);
            ldm4(A1, a_base + ks * 32 + 16 * PITCHB);
            ldm4(Bv0, bb + ks * 32);                 // nf0, nf1 (cols warp_n+0..15)
            ldm4(Bv1, bb + 16 * PITCHB + ks * 32);   // nf2, nf3 (cols warp_n+16..31)
            mma32(acc[0][0], A0, Bv0[0], Bv0[1]);
            mma32(acc[0][1], A0, Bv0[2], Bv0[3]);
            mma32(acc[0][2], A0, Bv1[0], Bv1[1]);
            mma32(acc[0][3], A0, Bv1[2], Bv1[3]);
            mma32(acc[1][0], A1, Bv0[0], Bv0[1]);
            mma32(acc[1][1], A1, Bv0[2], Bv0[3]);
            mma32(acc[1][2], A1, Bv1[0], Bv1[1]);
            mma32(acc[1][3], A1, Bv1[2], Bv1[3]);
        }

        // epilogue: v = acc*sc + (pk_j - pq_i); pair-exchange via shfl; STG.128
        float2 pkc0[2], pkc1[2];
        #pragma unroll
        for (int g = 0; g < 2; g++) {
            const int c0 = warp_n + g * 16 + (lane & 3) * 2;
            pkc0[g] = *(const float2*)(pkt + c0);
            pkc1[g] = *(const float2*)(pkt + c0 + 8);
        }
        #pragma unroll
        for (int mi = 0; mi < 2; mi++) {
            const int r = warp_m + mi * 16 + (lane >> 2);
            const float pq0 = pq[r], pq1 = pq[r + 8];
            float* orow = obase + (size_t)r * NS;
            #pragma unroll
            for (int g = 0; g < 2; g++) {
                float2 a0 = make_float2(fmaf(acc[mi][2 * g][0], sc, pkc0[g].x - pq0),
                                        fmaf(acc[mi][2 * g][1], sc, pkc0[g].y - pq0));
                float2 a1 = make_float2(fmaf(acc[mi][2 * g + 1][0], sc, pkc1[g].x - pq0),
                                        fmaf(acc[mi][2 * g + 1][1], sc, pkc1[g].y - pq0));
                float2 b0 = make_float2(fmaf(acc[mi][2 * g][2], sc, pkc0[g].x - pq1),
                                        fmaf(acc[mi][2 * g][3], sc, pkc0[g].y - pq1));
                float2 b1 = make_float2(fmaf(acc[mi][2 * g + 1][2], sc, pkc1[g].x - pq1),
                                        fmaf(acc[mi][2 * g + 1][3], sc, pkc1[g].y - pq1));
                float2 sa = odd ? a0 : a1;
                float2 sb = odd ? b0 : b1;
                float2 ra, rb;
                ra.x = __shfl_xor_sync(0xFFFFFFFF, sa.x, 1);
                ra.y = __shfl_xor_sync(0xFFFFFFFF, sa.y, 1);
                rb.x = __shfl_xor_sync(0xFFFFFFFF, sb.x, 1);
                rb.y = __shfl_xor_sync(0xFFFFFFFF, sb.y, 1);
                const int wc = wc_base + g * 16;
                float4 v0 = odd ? make_float4(ra.x, ra.y, a1.x, a1.y)
                                : make_float4(a0.x, a0.y, ra.x, ra.y);
                float4 v1 = odd ? make_float4(rb.x, rb.y, b1.x, b1.y)
                                : make_float4(b0.x, b0.y, rb.x, rb.y);
                __stcs((float4*)(orow + wc), v0);
                __stcs((float4*)(orow + (size_t)8 * NS + wc), v1);
            }
        }

        // advance loop-carried pointers; rotate buffers
        pkt += 64;
        obase += 64;
        uint32_t tmp = ld_cur;
        ld_cur = ld_nxt;
        ld_nxt = ld_n2;
        ld_n2  = tmp;
    }
}

// ---------------------------------------------------------------------------
// Launch
// ---------------------------------------------------------------------------
extern "C" void kernel_launch(void* const* d_in, const int* in_sizes, int n_in,
                              void* d_out, int out_size) {
    const float* q           = (const float*)d_in[0];
    const float* k           = (const float*)d_in[1];
    const float* head_scales = (const float*)d_in[2];
    const float* slopes      = (const float*)d_in[3];
    const float* positions   = (const float*)d_in[4];
    const int*   tok         = (const int*)d_in[5];
    float*       out         = (float*)d_out;

    // 8.39M floats per tensor / 8 per thread = 4096 blocks x 256
    prep_kernel<<<dim3(4096, 2), 256>>>(q, k);

    cudaFuncSetAttribute(alibi_gemm, cudaFuncAttributeMaxDynamicSharedMemorySize, SMEM_BYTES);
    alibi_gemm<<<dim3(8, 16, 32), 256, SMEM_BYTES>>>(head_scales, slopes, positions, tok, out);
}